// round 12
// baseline (speedup 1.0000x reference)
#include <cuda_runtime.h>

#define VOCABN 5000
#define NB 16
#define NS 128
#define NT 512
#define NL 257            // 2*NS + 1
#define ESTR 264          // ring row stride in floats (1056 B, 16B-aligned)
#define NRING 16          // ring rows per direction (2 chunks of 8)
#define ALPHA_W 0.2f
#define SMOOTH 0.1f
#define TM 255            // meet point

__device__ __forceinline__ float a2_into(const int* tb, int x) {
    if ((x & 1) && x >= 3 && x < NL) {
        int e  = __ldg(tb + (x >> 1));
        int ep = __ldg(tb + (x >> 1) - 1);
        return (e != 0 && e != ep) ? 1.0f : 0.0f;
    }
    return 0.0f;
}

__device__ __forceinline__ float warp_max_pos(float m) {
    // all operands non-negative -> fp32 ordering == u32 ordering
    return __uint_as_float(__reduce_max_sync(0xffffffffu, __float_as_uint(m)));
}

__global__ __launch_bounds__(512) void fused_kernel(
    const float* __restrict__ att,   // (16,128,5000)
    const float* __restrict__ ctc,   // (16,512,5000) log-probs per reference
    const int*   __restrict__ tgt,   // (16,128)
    float* __restrict__ out)
{
    __shared__ __align__(16) float ringF[NRING * ESTR];
    __shared__ __align__(16) float ringB[NRING * ESTR];
    __shared__ int flagF[32], flagB[32];
    __shared__ int consF, consB;
    __shared__ float aS[264], bS[264];
    __shared__ float sFS, sBS;
    __shared__ float red[16];

    const int tid = threadIdx.x;
    const int blk = blockIdx.x;

    if (blk < NB) {
        const int wid  = tid >> 5;
        const int lane = tid & 31;
        const float* cb = ctc + (size_t)blk * NT * VOCABN;
        const int*   tb = tgt + blk * NS;

        if (tid < 32) { flagF[tid] = 0; flagB[tid] = 0; }
        if (tid == 0) { consF = 0; consB = 0; }
        __syncthreads();

        if (wid >= 2) {
            // ================= producer warps =================
            const bool fwd = (wid < 9);
            const int  pw  = fwd ? (wid - 2) : (wid - 9);      // 0..6
            volatile int* myCons = fwd ? &consF : &consB;
            int*  myFlag = fwd ? flagF : flagB;
            float* ring  = fwd ? ringF : ringB;
            // ext targets for this lane's odd states 8l+{1,3,5,7}
            const int e0 = __ldg(tb + 4 * lane + 0);
            const int e1 = __ldg(tb + 4 * lane + 1);
            const int e2 = __ldg(tb + 4 * lane + 2);
            const int e3 = __ldg(tb + 4 * lane + 3);

            for (int c = pw; c < 32; c += 7) {
                while (*myCons < c - 1) { }                     // 2-chunk ring throttle
                const int k0 = c * 8;
                const int kend = (k0 + 8 < 255) ? k0 + 8 : 255;
                #pragma unroll 2
                for (int k = k0; k < kend; ++k) {
                    const int t = fwd ? (1 + k) : (510 - k);
                    const float* rowp = cb + (size_t)t * VOCABN;
                    float b0 = __ldg(rowp);                      // blank (broadcast)
                    float o1 = __ldg(rowp + e0);
                    float o3 = __ldg(rowp + e1);
                    float o5 = __ldg(rowp + e2);
                    float o7 = __ldg(rowp + e3);
                    float bE = __expf(b0);
                    o1 = __expf(o1); o3 = __expf(o3);
                    o5 = __expf(o5); o7 = __expf(o7);
                    float* dst = &ring[(k & (NRING - 1)) * ESTR + 8 * lane];
                    *(float4*)dst       = make_float4(bE, o1, bE, o3);
                    *(float4*)(dst + 4) = make_float4(bE, o5, bE, o7);
                }
                __syncwarp();
                __threadfence_block();
                if (lane == 0) *(volatile int*)&myFlag[c] = 1;
                __syncwarp();
            }
        } else if (tid < 32) {
            // ================= forward consumer: t = 1..255 =================
            float a2[8];
            #pragma unroll
            for (int j = 0; j < 8; ++j) a2[j] = a2_into(tb, 8 * lane + j);

            float v[8], v8 = 0.0f;
            #pragma unroll
            for (int j = 0; j < 8; ++j) v[j] = 0.0f;
            if (lane == 0) {
                v[0] = __expf(__ldg(cb + 0));
                v[1] = __expf(__ldg(cb + __ldg(tb + 0)));
            }

            float sF = 0.0f;
            for (int tt = 0; tt < 32; ++tt) {
                while (*(volatile int*)&flagF[tt] == 0) { }
                #pragma unroll
                for (int i = 0; i < 8; ++i) {
                    const int k = tt * 8 + i;                    // t = k+1
                    if (k < 255) {
                        const float* rs = &ringF[(k & (NRING - 1)) * ESTR + 8 * lane];
                        float4 EA = *(const float4*)rs;
                        float4 EB = *(const float4*)(rs + 4);
                        float E8 = __shfl_sync(0xffffffffu, EA.x, 0);  // blank
                        float x1 = __shfl_up_sync(0xffffffffu, v[7], 1);
                        float x2 = __shfl_up_sync(0xffffffffu, v[6], 1);
                        if (lane == 0) { x1 = 0.0f; x2 = 0.0f; }
                        float n0 = (v[0] + x1)   + a2[0] * x2;
                        float n1 = (v[1] + v[0]) + a2[1] * x1;
                        float n2 = (v[2] + v[1]) + a2[2] * v[0];
                        float n3 = (v[3] + v[2]) + a2[3] * v[1];
                        float n4 = (v[4] + v[3]) + a2[4] * v[2];
                        float n5 = (v[5] + v[4]) + a2[5] * v[3];
                        float n6 = (v[6] + v[5]) + a2[6] * v[4];
                        float n7 = (v[7] + v[6]) + a2[7] * v[5];
                        float n8 = v8 + v[7];
                        v[0] = n0 * EA.x; v[1] = n1 * EA.y;
                        v[2] = n2 * EA.z; v[3] = n3 * EA.w;
                        v[4] = n4 * EB.x; v[5] = n5 * EB.y;
                        v[6] = n6 * EB.z; v[7] = n7 * EB.w;
                        v8   = n8 * E8;
                    }
                }
                float m01 = fmaxf(v[0], v[1]), m23 = fmaxf(v[2], v[3]);
                float m45 = fmaxf(v[4], v[5]), m67 = fmaxf(v[6], v[7]);
                float m = fmaxf(fmaxf(m01, m23), fmaxf(fmaxf(m45, m67), v8));
                m = warp_max_pos(m);
                float r = __fdividef(1.0f, m);
                #pragma unroll
                for (int j = 0; j < 8; ++j) v[j] *= r;
                v8 *= r;
                sF += __logf(m);
                if (lane == 0) *(volatile int*)&consF = tt + 1;  // release ring
            }
            #pragma unroll
            for (int j = 0; j < 8; ++j) aS[8 * lane + j] = v[j];
            if (lane == 31) aS[256] = v8;
            if (lane == 0) sFS = sF;
        } else {
            // ================= backward consumer: t = 510..256 (init 511) =================
            float a2b[8];
            #pragma unroll
            for (int j = 0; j < 8; ++j) a2b[j] = a2_into(tb, 8 * lane + j + 2);

            float v[8], v8 = 0.0f;
            #pragma unroll
            for (int j = 0; j < 8; ++j) v[j] = 0.0f;
            if (lane == 31) {
                const float* r511 = cb + (size_t)511 * VOCABN;
                v[7] = __expf(__ldg(r511 + __ldg(tb + 127)));   // state 255
                v8   = __expf(__ldg(r511));                      // state 256 = blank
            }

            float sB = 0.0f;
            for (int tt = 0; tt < 32; ++tt) {
                while (*(volatile int*)&flagB[tt] == 0) { }
                #pragma unroll
                for (int i = 0; i < 8; ++i) {
                    const int k = tt * 8 + i;                    // t = 510-k
                    if (k < 255) {
                        const float* rs = &ringB[(k & (NRING - 1)) * ESTR + 8 * lane];
                        float4 EA = *(const float4*)rs;
                        float4 EB = *(const float4*)(rs + 4);
                        float E8 = __shfl_sync(0xffffffffu, EA.x, 0);
                        float x1 = __shfl_down_sync(0xffffffffu, v[0], 1); // state 8l+8
                        float x2 = __shfl_down_sync(0xffffffffu, v[1], 1); // state 8l+9
                        if (lane == 31) { x1 = v8; x2 = 0.0f; }
                        float n0 = (v[0] + v[1]) + a2b[0] * v[2];
                        float n1 = (v[1] + v[2]) + a2b[1] * v[3];
                        float n2 = (v[2] + v[3]) + a2b[2] * v[4];
                        float n3 = (v[3] + v[4]) + a2b[3] * v[5];
                        float n4 = (v[4] + v[5]) + a2b[4] * v[6];
                        float n5 = (v[5] + v[6]) + a2b[5] * v[7];
                        float n6 = (v[6] + v[7]) + a2b[6] * x1;
                        float n7 = (v[7] + x1)   + a2b[7] * x2;
                        float n8 = v8;                           // state 256: self only
                        v[0] = n0 * EA.x; v[1] = n1 * EA.y;
                        v[2] = n2 * EA.z; v[3] = n3 * EA.w;
                        v[4] = n4 * EB.x; v[5] = n5 * EB.y;
                        v[6] = n6 * EB.z; v[7] = n7 * EB.w;
                        v8   = n8 * E8;
                    }
                }
                float m01 = fmaxf(v[0], v[1]), m23 = fmaxf(v[2], v[3]);
                float m45 = fmaxf(v[4], v[5]), m67 = fmaxf(v[6], v[7]);
                float m = fmaxf(fmaxf(m01, m23), fmaxf(fmaxf(m45, m67), v8));
                m = warp_max_pos(m);
                float r = __fdividef(1.0f, m);
                #pragma unroll
                for (int j = 0; j < 8; ++j) v[j] *= r;
                v8 *= r;
                sB += __logf(m);
                if (lane == 0) *(volatile int*)&consB = tt + 1;
            }
            #pragma unroll
            for (int j = 0; j < 8; ++j) bS[8 * lane + j] = v[j];
            if (lane == 31) { bS[256] = v8; bS[257] = 0.0f; bS[258] = 0.0f; }
            if (lane == 0) sBS = sB;
        }

        __syncthreads();

        if (tid < 32) {
            const int lane = tid;
            float dot = 0.0f;
            #pragma unroll
            for (int j = 0; j < 8; ++j) {
                int s = 8 * lane + j;
                float C = bS[s] + bS[s + 1] + a2_into(tb, s + 2) * bS[s + 2];
                dot += aS[s] * C;
            }
            if (lane == 31) dot += aS[256] * bS[256];
            #pragma unroll
            for (int o = 16; o > 0; o >>= 1)
                dot += __shfl_xor_sync(0xffffffffu, dot, o);
            if (lane == 0) {
                float ll = __logf(dot) + sFS + sBS;
                float lb = -ll;
                if (!(lb < 1e20f)) lb = 0.0f;      // zero_infinity (inf/nan too)
                atomicAdd(out, ((1.0f - ALPHA_W) / (float)(NB * NS)) * lb);
            }
        }
    } else {
        // ================= label-smoothing row `blk - NB` =================
        const int r = blk - NB;
        const float* row = att + (size_t)r * VOCABN;
        const int tv = __ldg(tgt + r);

        float s = 0.0f;
        const float4* row4 = (const float4*)row;   // 5000 % 4 == 0
        for (int i = tid; i < VOCABN / 4; i += 512) {
            float4 v = row4[i];
            s += (v.x + v.y) + (v.z + v.w);
        }
        #pragma unroll
        for (int o = 16; o > 0; o >>= 1)
            s += __shfl_down_sync(0xffffffffu, s, o);
        const int wid = tid >> 5, lane = tid & 31;
        if (lane == 0) red[wid] = s;
        __syncthreads();
        if (tid == 0) {
            float total = 0.0f;
            #pragma unroll
            for (int w = 0; w < 16; ++w) total += red[w];
            float tl = __ldg(row + tv);
            const float conf = 1.0f - SMOOTH;
            const float off  = SMOOTH / (float)(VOCABN - 1);
            float per_row = -(off * total + (conf - off) * tl);
            atomicAdd(out, (ALPHA_W / 2048.0f) * per_row);
        }
    }
}

extern "C" void kernel_launch(void* const* d_in, const int* in_sizes, int n_in,
                              void* d_out, int out_size) {
    const float* att = (const float*)d_in[0];
    const float* ctc = (const float*)d_in[1];
    const int*   tgt = (const int*)d_in[2];
    float* out = (float*)d_out;

    cudaMemsetAsync(out, 0, sizeof(float));
    fused_kernel<<<NB + NB * NS, 512>>>(att, ctc, tgt, out);
}

// round 13
// speedup vs baseline: 1.4379x; 1.4379x over previous
#include <cuda_runtime.h>

#define VOCABN 5000
#define NB 16
#define NS 128
#define NT 512
#define NL 257            // 2*NS + 1
#define RS 256            // ring row stride in floats (1 KB)
#define NRING 64          // ring rows per direction = 8 chunks of 8
#define NCHUNK 8
#define ALPHA_W 0.2f
#define SMOOTH 0.1f
#define DYN_SMEM (2 * NRING * RS * 4)   // 128 KB

__device__ __forceinline__ float a2_into(const int* tb, int x) {
    if ((x & 1) && x >= 3 && x < NL) {
        int e  = __ldg(tb + (x >> 1));
        int ep = __ldg(tb + (x >> 1) - 1);
        return (e != 0 && e != ep) ? 1.0f : 0.0f;
    }
    return 0.0f;
}

__device__ __forceinline__ float warp_max_pos(float m) {
    // all operands non-negative -> fp32 ordering == u32 ordering
    return __uint_as_float(__reduce_max_sync(0xffffffffu, __float_as_uint(m)));
}

__global__ __launch_bounds__(512) void fused_kernel(
    const float* __restrict__ att,   // (16,128,5000)
    const float* __restrict__ ctc,   // (16,512,5000) log-probs per reference
    const int*   __restrict__ tgt,   // (16,128)
    float* __restrict__ out)
{
    extern __shared__ __align__(16) float dynS[];   // [ringF | ringB], 64KB each
    __shared__ int flagF[32], flagB[32];
    __shared__ int consF, consB;
    __shared__ float aS[264], bS[264];
    __shared__ float sFS, sBS;
    __shared__ float red[16];

    const int tid = threadIdx.x;
    const int blk = blockIdx.x;

    if (blk < NB) {
        float* ringF = dynS;
        float* ringB = dynS + NRING * RS;
        const int wid  = tid >> 5;
        const int lane = tid & 31;
        const float* cb = ctc + (size_t)blk * NT * VOCABN;
        const int*   tb = tgt + blk * NS;

        if (tid < 32) { flagF[tid] = 0; flagB[tid] = 0; }
        if (tid == 0) { consF = 0; consB = 0; }
        __syncthreads();

        if (wid >= 2) {
            // ================= producer warps (7 fwd, 7 bwd) =================
            const bool fwd = (wid < 9);
            const int  pw  = fwd ? (wid - 2) : (wid - 9);      // 0..6
            volatile int* myCons = fwd ? &consF : &consB;
            int*  myFlag = fwd ? flagF : flagB;
            float* ring  = fwd ? ringF : ringB;
            // ext targets for this lane's odd states 8l+{1,3,5,7}
            const int e0 = __ldg(tb + 4 * lane + 0);
            const int e1 = __ldg(tb + 4 * lane + 1);
            const int e2 = __ldg(tb + 4 * lane + 2);
            const int e3 = __ldg(tb + 4 * lane + 3);

            for (int c = pw; c < 32; c += 7) {
                while (*myCons < c - (NCHUNK - 1)) { }          // 8-chunk ring throttle
                const int k0 = c * 8;
                const int kend = (k0 + 8 < 255) ? k0 + 8 : 255;
                #pragma unroll 2
                for (int k = k0; k < kend; ++k) {
                    const int t = fwd ? (1 + k) : (510 - k);
                    const float* rowp = cb + (size_t)t * VOCABN;
                    float b0 = __ldg(rowp);                      // blank (broadcast)
                    float o1 = __ldg(rowp + e0);
                    float o3 = __ldg(rowp + e1);
                    float o5 = __ldg(rowp + e2);
                    float o7 = __ldg(rowp + e3);
                    float bE = __expf(b0);
                    o1 = __expf(o1); o3 = __expf(o3);
                    o5 = __expf(o5); o7 = __expf(o7);
                    float* dst = &ring[(k & (NRING - 1)) * RS + 8 * lane];
                    *(float4*)dst       = make_float4(bE, o1, bE, o3);
                    *(float4*)(dst + 4) = make_float4(bE, o5, bE, o7);
                }
                __syncwarp();
                __threadfence_block();
                if (lane == 0) *(volatile int*)&myFlag[c] = 1;
                __syncwarp();
            }
        } else if (tid < 32) {
            // ================= forward consumer: t = 1..255 =================
            float a2[8];
            #pragma unroll
            for (int j = 0; j < 8; ++j) a2[j] = a2_into(tb, 8 * lane + j);

            float v[8], v8 = 0.0f;
            #pragma unroll
            for (int j = 0; j < 8; ++j) v[j] = 0.0f;
            if (lane == 0) {
                v[0] = __expf(__ldg(cb + 0));
                v[1] = __expf(__ldg(cb + __ldg(tb + 0)));
            }

            float sF = 0.0f;
            for (int tt = 0; tt < 32; ++tt) {
                while (*(volatile int*)&flagF[tt] == 0) { }
                #pragma unroll
                for (int i = 0; i < 8; ++i) {
                    const int k = tt * 8 + i;                    // t = k+1
                    if (k < 255) {
                        const float* rs = &ringF[(k & (NRING - 1)) * RS + 8 * lane];
                        float4 EA = *(const float4*)rs;
                        float4 EB = *(const float4*)(rs + 4);
                        float E8 = __shfl_sync(0xffffffffu, EA.x, 0);  // blank
                        float x1 = __shfl_up_sync(0xffffffffu, v[7], 1);
                        float x2 = __shfl_up_sync(0xffffffffu, v[6], 1);
                        if (lane == 0) { x1 = 0.0f; x2 = 0.0f; }
                        float n0 = (v[0] + x1)   + a2[0] * x2;
                        float n1 = (v[1] + v[0]) + a2[1] * x1;
                        float n2 = (v[2] + v[1]) + a2[2] * v[0];
                        float n3 = (v[3] + v[2]) + a2[3] * v[1];
                        float n4 = (v[4] + v[3]) + a2[4] * v[2];
                        float n5 = (v[5] + v[4]) + a2[5] * v[3];
                        float n6 = (v[6] + v[5]) + a2[6] * v[4];
                        float n7 = (v[7] + v[6]) + a2[7] * v[5];
                        float n8 = v8 + v[7];
                        v[0] = n0 * EA.x; v[1] = n1 * EA.y;
                        v[2] = n2 * EA.z; v[3] = n3 * EA.w;
                        v[4] = n4 * EB.x; v[5] = n5 * EB.y;
                        v[6] = n6 * EB.z; v[7] = n7 * EB.w;
                        v8   = n8 * E8;
                    }
                }
                float m01 = fmaxf(v[0], v[1]), m23 = fmaxf(v[2], v[3]);
                float m45 = fmaxf(v[4], v[5]), m67 = fmaxf(v[6], v[7]);
                float m = fmaxf(fmaxf(m01, m23), fmaxf(fmaxf(m45, m67), v8));
                m = warp_max_pos(m);
                float r = __fdividef(1.0f, m);
                #pragma unroll
                for (int j = 0; j < 8; ++j) v[j] *= r;
                v8 *= r;
                sF += __logf(m);
                if (lane == 0) *(volatile int*)&consF = tt + 1;  // release ring
            }
            #pragma unroll
            for (int j = 0; j < 8; ++j) aS[8 * lane + j] = v[j];
            if (lane == 31) aS[256] = v8;
            if (lane == 0) sFS = sF;
        } else {
            // ================= backward consumer: t = 510..256 (init 511) =================
            float a2b[8];
            #pragma unroll
            for (int j = 0; j < 8; ++j) a2b[j] = a2_into(tb, 8 * lane + j + 2);

            float v[8], v8 = 0.0f;
            #pragma unroll
            for (int j = 0; j < 8; ++j) v[j] = 0.0f;
            if (lane == 31) {
                const float* r511 = cb + (size_t)511 * VOCABN;
                v[7] = __expf(__ldg(r511 + __ldg(tb + 127)));   // state 255
                v8   = __expf(__ldg(r511));                      // state 256 = blank
            }

            float sB = 0.0f;
            for (int tt = 0; tt < 32; ++tt) {
                while (*(volatile int*)&flagB[tt] == 0) { }
                #pragma unroll
                for (int i = 0; i < 8; ++i) {
                    const int k = tt * 8 + i;                    // t = 510-k
                    if (k < 255) {
                        const float* rs = &ringB[(k & (NRING - 1)) * RS + 8 * lane];
                        float4 EA = *(const float4*)rs;
                        float4 EB = *(const float4*)(rs + 4);
                        float E8 = __shfl_sync(0xffffffffu, EA.x, 0);
                        float x1 = __shfl_down_sync(0xffffffffu, v[0], 1); // state 8l+8
                        float x2 = __shfl_down_sync(0xffffffffu, v[1], 1); // state 8l+9
                        if (lane == 31) { x1 = v8; x2 = 0.0f; }
                        float n0 = (v[0] + v[1]) + a2b[0] * v[2];
                        float n1 = (v[1] + v[2]) + a2b[1] * v[3];
                        float n2 = (v[2] + v[3]) + a2b[2] * v[4];
                        float n3 = (v[3] + v[4]) + a2b[3] * v[5];
                        float n4 = (v[4] + v[5]) + a2b[4] * v[6];
                        float n5 = (v[5] + v[6]) + a2b[5] * v[7];
                        float n6 = (v[6] + v[7]) + a2b[6] * x1;
                        float n7 = (v[7] + x1)   + a2b[7] * x2;
                        float n8 = v8;                           // state 256: self only
                        v[0] = n0 * EA.x; v[1] = n1 * EA.y;
                        v[2] = n2 * EA.z; v[3] = n3 * EA.w;
                        v[4] = n4 * EB.x; v[5] = n5 * EB.y;
                        v[6] = n6 * EB.z; v[7] = n7 * EB.w;
                        v8   = n8 * E8;
                    }
                }
                float m01 = fmaxf(v[0], v[1]), m23 = fmaxf(v[2], v[3]);
                float m45 = fmaxf(v[4], v[5]), m67 = fmaxf(v[6], v[7]);
                float m = fmaxf(fmaxf(m01, m23), fmaxf(fmaxf(m45, m67), v8));
                m = warp_max_pos(m);
                float r = __fdividef(1.0f, m);
                #pragma unroll
                for (int j = 0; j < 8; ++j) v[j] *= r;
                v8 *= r;
                sB += __logf(m);
                if (lane == 0) *(volatile int*)&consB = tt + 1;
            }
            #pragma unroll
            for (int j = 0; j < 8; ++j) bS[8 * lane + j] = v[j];
            if (lane == 31) { bS[256] = v8; bS[257] = 0.0f; bS[258] = 0.0f; }
            if (lane == 0) sBS = sB;
        }

        __syncthreads();

        if (tid < 32) {
            const int lane = tid;
            float dot = 0.0f;
            #pragma unroll
            for (int j = 0; j < 8; ++j) {
                int s = 8 * lane + j;
                float C = bS[s] + bS[s + 1] + a2_into(tb, s + 2) * bS[s + 2];
                dot += aS[s] * C;
            }
            if (lane == 31) dot += aS[256] * bS[256];
            #pragma unroll
            for (int o = 16; o > 0; o >>= 1)
                dot += __shfl_xor_sync(0xffffffffu, dot, o);
            if (lane == 0) {
                float ll = __logf(dot) + sFS + sBS;
                float lb = -ll;
                if (!(lb < 1e20f)) lb = 0.0f;      // zero_infinity (inf/nan too)
                atomicAdd(out, ((1.0f - ALPHA_W) / (float)(NB * NS)) * lb);
            }
        }
    } else {
        // ================= label-smoothing row `blk - NB` =================
        const int r = blk - NB;
        const float* row = att + (size_t)r * VOCABN;
        const int tv = __ldg(tgt + r);

        float s = 0.0f;
        const float4* row4 = (const float4*)row;   // 5000 % 4 == 0
        for (int i = tid; i < VOCABN / 4; i += 512) {
            float4 v = row4[i];
            s += (v.x + v.y) + (v.z + v.w);
        }
        #pragma unroll
        for (int o = 16; o > 0; o >>= 1)
            s += __shfl_down_sync(0xffffffffu, s, o);
        const int wid = tid >> 5, lane = tid & 31;
        if (lane == 0) red[wid] = s;
        __syncthreads();
        if (tid == 0) {
            float total = 0.0f;
            #pragma unroll
            for (int w = 0; w < 16; ++w) total += red[w];
            float tl = __ldg(row + tv);
            const float conf = 1.0f - SMOOTH;
            const float off  = SMOOTH / (float)(VOCABN - 1);
            float per_row = -(off * total + (conf - off) * tl);
            atomicAdd(out, (ALPHA_W / 2048.0f) * per_row);
        }
    }
}

extern "C" void kernel_launch(void* const* d_in, const int* in_sizes, int n_in,
                              void* d_out, int out_size) {
    const float* att = (const float*)d_in[0];
    const float* ctc = (const float*)d_in[1];
    const int*   tgt = (const int*)d_in[2];
    float* out = (float*)d_out;

    cudaFuncSetAttribute(fused_kernel,
                         cudaFuncAttributeMaxDynamicSharedMemorySize, DYN_SMEM);
    cudaMemsetAsync(out, 0, sizeof(float));
    fused_kernel<<<NB + NB * NS, 512, DYN_SMEM>>>(att, ctc, tgt, out);
}